// round 1
// baseline (speedup 1.0000x reference)
#include <cuda_runtime.h>
#include <cstdint>

// 1 = modern JAX (jax_threefry_partitionable=True, default since ~0.4.36)
// 0 = legacy threefry split/random_bits
#define JAX_PARTITIONABLE 1

#define BB 2
#define CC 512
#define LQ 2048
#define LC 4096
#define HH 8
#define DD 64
#define BHH 16
#define TK 512
#define INNER 512

// ---------------- scratch (device globals; no allocation allowed) ----------------
__device__ float g_ctxn[BB * CC * LC];
__device__ float g_qsn[BB * CC * LQ];
__device__ float g_kv[BB * 2 * INNER * LC];
__device__ float g_qpr[BB * INNER * LQ];
__device__ float g_karr[BHH * LC * DD];   // (bh, l, d) L2-normalized k
__device__ float g_varr[BHH * LC * DD];   // (bh, l, d) v
__device__ float g_qarr[BHH * LQ * DD];   // (bh, l, d) L2-normalized q
__device__ float g_qsm[BHH * TK * DD];    // gathered random Q rows
__device__ float g_mind[BHH * LC];
__device__ int g_ridx[BHH * TK];
__device__ int g_sidx[BHH * TK];
__device__ float g_ksel[BHH * TK * DD];
__device__ float g_vsel[BHH * TK * DD];
__device__ float g_attnT[BB * INNER * LQ]; // (b, i=h*64+d, l)
__device__ float g_proj[BB * CC * LQ];

// ---------------- Threefry-2x32 (20 rounds), matches JAX ----------------
__device__ __forceinline__ void tf2x32(unsigned k0, unsigned k1, unsigned x0,
                                       unsigned x1, unsigned& y0, unsigned& y1) {
    unsigned ks2 = k0 ^ k1 ^ 0x1BD11BDAu;
    x0 += k0; x1 += k1;
#define TFR(r) { x0 += x1; x1 = (x1 << (r)) | (x1 >> (32 - (r))); x1 ^= x0; }
    TFR(13) TFR(15) TFR(26) TFR(6)
    x0 += k1; x1 += ks2 + 1u;
    TFR(17) TFR(29) TFR(16) TFR(24)
    x0 += ks2; x1 += k0 + 2u;
    TFR(13) TFR(15) TFR(26) TFR(6)
    x0 += k0; x1 += k1 + 3u;
    TFR(17) TFR(29) TFR(16) TFR(24)
    x0 += k1; x1 += ks2 + 4u;
    TFR(13) TFR(15) TFR(26) TFR(6)
    x0 += ks2; x1 += k0 + 5u;
#undef TFR
    y0 = x0; y1 = x1;
}

__global__ void rng_kernel() {
    int i = blockIdx.x * blockDim.x + threadIdx.x;  // 0..8191
    if (i >= BHH * TK) return;
    unsigned bits;
#if JAX_PARTITIONABLE
    // split (foldlike): k2 = TF(key, (0,1)); bits[i] = y0^y1 of TF(k2, (0,i))
    unsigned k2a, k2b;
    tf2x32(0u, 42u, 0u, 1u, k2a, k2b);
    unsigned y0, y1;
    tf2x32(k2a, k2b, 0u, (unsigned)i, y0, y1);
    bits = y0 ^ y1;
#else
    // original: split counts [0,1,2,3] -> lanes (0,2),(1,3); k2 = second output words
    unsigned a0, a1, b0, b1;
    tf2x32(0u, 42u, 0u, 2u, a0, a1);
    tf2x32(0u, 42u, 1u, 3u, b0, b1);
    unsigned k2a = a1, k2b = b1;
    int lane = (i < 4096) ? i : i - 4096;
    unsigned y0, y1;
    tf2x32(k2a, k2b, (unsigned)lane, (unsigned)(lane + 4096), y0, y1);
    bits = (i < 4096) ? y0 : y1;
#endif
    g_ridx[i] = (int)(bits & 2047u);
}

// ---------------- channel LayerNorm: (b, C, L), normalize over C ----------------
__global__ void chan_ln_kernel(const float* __restrict__ x, const float* __restrict__ gw,
                               const float* __restrict__ bw, float* __restrict__ y,
                               int C, int L) {
    int b = blockIdx.y;
    int l = blockIdx.x * 32 + threadIdx.x;
    const float* xb = x + (size_t)b * C * L;
    float s = 0.f, s2 = 0.f;
    for (int c = threadIdx.y; c < C; c += 8) {
        float v = xb[(size_t)c * L + l];
        s += v; s2 += v * v;
    }
    __shared__ float sh_s[8][32], sh_s2[8][32];
    sh_s[threadIdx.y][threadIdx.x] = s;
    sh_s2[threadIdx.y][threadIdx.x] = s2;
    __syncthreads();
    if (threadIdx.y == 0) {
        float ts = 0.f, t2 = 0.f;
        #pragma unroll
        for (int i = 0; i < 8; i++) { ts += sh_s[i][threadIdx.x]; t2 += sh_s2[i][threadIdx.x]; }
        float mean = ts / (float)C;
        float var = t2 / (float)C - mean * mean;
        sh_s[0][threadIdx.x] = mean;
        sh_s2[0][threadIdx.x] = rsqrtf(var + 1e-5f);
    }
    __syncthreads();
    float mean = sh_s[0][threadIdx.x];
    float rstd = sh_s2[0][threadIdx.x];
    float* yb = y + (size_t)b * C * L;
    for (int c = threadIdx.y; c < C; c += 8) {
        float v = xb[(size_t)c * L + l];
        yb[(size_t)c * L + l] = (v - mean) * rstd * gw[c] + bw[c];
    }
}

// final LN + gamma*out + residual
__global__ void final_ln_kernel(const float* __restrict__ x, const float* __restrict__ gw,
                                const float* __restrict__ bw, const float* __restrict__ res,
                                const float* __restrict__ gamma, float* __restrict__ y,
                                int C, int L) {
    int b = blockIdx.y;
    int l = blockIdx.x * 32 + threadIdx.x;
    const float* xb = x + (size_t)b * C * L;
    float s = 0.f, s2 = 0.f;
    for (int c = threadIdx.y; c < C; c += 8) {
        float v = xb[(size_t)c * L + l];
        s += v; s2 += v * v;
    }
    __shared__ float sh_s[8][32], sh_s2[8][32];
    sh_s[threadIdx.y][threadIdx.x] = s;
    sh_s2[threadIdx.y][threadIdx.x] = s2;
    __syncthreads();
    if (threadIdx.y == 0) {
        float ts = 0.f, t2 = 0.f;
        #pragma unroll
        for (int i = 0; i < 8; i++) { ts += sh_s[i][threadIdx.x]; t2 += sh_s2[i][threadIdx.x]; }
        float mean = ts / (float)C;
        float var = t2 / (float)C - mean * mean;
        sh_s[0][threadIdx.x] = mean;
        sh_s2[0][threadIdx.x] = rsqrtf(var + 1e-5f);
    }
    __syncthreads();
    float mean = sh_s[0][threadIdx.x];
    float rstd = sh_s2[0][threadIdx.x];
    float gm = gamma[0];
    const float* rb = res + (size_t)b * C * L;
    float* yb = y + (size_t)b * C * L;
    for (int c = threadIdx.y; c < C; c += 8) {
        float v = xb[(size_t)c * L + l];
        yb[(size_t)c * L + l] = gm * ((v - mean) * rstd * gw[c] + bw[c]) + rb[(size_t)c * L + l];
    }
}

// ---------------- SGEMM: C[b] = A(MxK) @ B[b](KxN), all row-major ----------------
__global__ void __launch_bounds__(256) sgemm128(const float* __restrict__ A,
                                                const float* __restrict__ Bsrc,
                                                float* __restrict__ Csrc, int M, int N,
                                                int K, size_t bStride, size_t cStride) {
    const float* B = Bsrc + (size_t)blockIdx.z * bStride;
    float* C = Csrc + (size_t)blockIdx.z * cStride;
    int bm = blockIdx.y * 128;
    int bn = blockIdx.x * 128;
    __shared__ float As[8][128];
    __shared__ float Bs[8][128];
    int tid = threadIdx.x;
    int tx = tid & 15, ty = tid >> 4;
    float acc[8][8];
    #pragma unroll
    for (int i = 0; i < 8; i++)
        #pragma unroll
        for (int j = 0; j < 8; j++) acc[i][j] = 0.f;
    int aRow = tid >> 1;
    int aCol = (tid & 1) * 4;
    int bRow = tid >> 5;
    int bCol = (tid & 31) * 4;
    const float* Aptr = A + (size_t)(bm + aRow) * K + aCol;
    const float* Bptr = B + (size_t)bRow * N + bn + bCol;
    for (int k0 = 0; k0 < K; k0 += 8) {
        float4 av = *reinterpret_cast<const float4*>(Aptr + k0);
        float4 bv = *reinterpret_cast<const float4*>(Bptr + (size_t)k0 * N);
        As[aCol + 0][aRow] = av.x; As[aCol + 1][aRow] = av.y;
        As[aCol + 2][aRow] = av.z; As[aCol + 3][aRow] = av.w;
        *reinterpret_cast<float4*>(&Bs[bRow][bCol]) = bv;
        __syncthreads();
        #pragma unroll
        for (int kk = 0; kk < 8; kk++) {
            float ar[8], br[8];
            *(float4*)&ar[0] = *(float4*)&As[kk][ty * 8];
            *(float4*)&ar[4] = *(float4*)&As[kk][ty * 8 + 4];
            *(float4*)&br[0] = *(float4*)&Bs[kk][tx * 8];
            *(float4*)&br[4] = *(float4*)&Bs[kk][tx * 8 + 4];
            #pragma unroll
            for (int i = 0; i < 8; i++)
                #pragma unroll
                for (int j = 0; j < 8; j++) acc[i][j] += ar[i] * br[j];
        }
        __syncthreads();
    }
    #pragma unroll
    for (int i = 0; i < 8; i++) {
        float* crow = C + (size_t)(bm + ty * 8 + i) * N + bn + tx * 8;
        *(float4*)crow = make_float4(acc[i][0], acc[i][1], acc[i][2], acc[i][3]);
        *(float4*)(crow + 4) = make_float4(acc[i][4], acc[i][5], acc[i][6], acc[i][7]);
    }
}

// ---------------- (b, o<512, l) -> (bh, l, d) head transpose ----------------
__global__ void head_transpose(const float* __restrict__ src, float* __restrict__ dst,
                               int L, size_t srcBatchStride) {
    __shared__ float tile[32][33];
    int b = blockIdx.z;
    int o0 = blockIdx.y * 32;
    int l0 = blockIdx.x * 32;
    const float* s = src + (size_t)b * srcBatchStride;
    #pragma unroll
    for (int k = 0; k < 4; k++) {
        int o = o0 + threadIdx.y + k * 8;
        tile[threadIdx.y + k * 8][threadIdx.x] = s[(size_t)o * L + l0 + threadIdx.x];
    }
    __syncthreads();
    int h = o0 >> 6;
    int dbase = o0 & 63;
    float* dph = dst + (size_t)(b * HH + h) * L * DD;
    #pragma unroll
    for (int k = 0; k < 4; k++) {
        int row = threadIdx.y + k * 8;  // l offset
        int col = threadIdx.x;          // d offset
        dph[(size_t)(l0 + row) * DD + dbase + col] = tile[col][row];
    }
}

// ---------------- L2 normalize rows of 64 ----------------
__global__ void l2norm_rows(float* __restrict__ x) {
    int row = blockIdx.x * 8 + threadIdx.y;
    float* p = x + (size_t)row * DD;
    int lane = threadIdx.x;
    float a = p[lane], b = p[lane + 32];
    float s = a * a + b * b;
    #pragma unroll
    for (int o = 16; o > 0; o >>= 1) s += __shfl_xor_sync(0xFFFFFFFFu, s, o);
    float n = sqrtf(s);
    float inv = 1.0f / fmaxf(n, 1e-12f);
    p[lane] = a * inv;
    p[lane + 32] = b * inv;
}

// ---------------- gathers ----------------
__global__ void gather_qsmall() {
    int r = blockIdx.x * 8 + threadIdx.y;  // 0..BHH*TK-1
    int bh = r >> 9;
    int idx = g_ridx[r];
    const float* s = g_qarr + ((size_t)bh * LQ + idx) * DD;
    float* d = g_qsm + (size_t)r * DD;
    d[threadIdx.x] = s[threadIdx.x];
    d[threadIdx.x + 32] = s[threadIdx.x + 32];
}

__global__ void gather_sel() {
    int r = blockIdx.x * 8 + threadIdx.y;
    int bh = r >> 9;
    int idx = g_sidx[r];
    const float* ks = g_karr + ((size_t)bh * LC + idx) * DD;
    const float* vs = g_varr + ((size_t)bh * LC + idx) * DD;
    g_ksel[(size_t)r * DD + threadIdx.x] = ks[threadIdx.x];
    g_ksel[(size_t)r * DD + 32 + threadIdx.x] = ks[threadIdx.x + 32];
    g_vsel[(size_t)r * DD + threadIdx.x] = vs[threadIdx.x];
    g_vsel[(size_t)r * DD + 32 + threadIdx.x] = vs[threadIdx.x + 32];
}

// ---------------- L1 min-distance: thread per k, q tiles in smem ----------------
__global__ void __launch_bounds__(256, 2) l1_min_kernel() {
    int bh = blockIdx.y;
    int kl = blockIdx.x * 256 + threadIdx.x;
    const float4* kp = reinterpret_cast<const float4*>(g_karr + ((size_t)bh * LC + kl) * DD);
    float kr[DD];
    #pragma unroll
    for (int i = 0; i < 16; i++) {
        float4 v = kp[i];
        kr[4 * i] = v.x; kr[4 * i + 1] = v.y; kr[4 * i + 2] = v.z; kr[4 * i + 3] = v.w;
    }
    __shared__ float4 qs[128 * 16];  // 128 q rows x 64 floats = 32KB
    float best = 3.4e38f;
    for (int qc = 0; qc < TK; qc += 128) {
        const float4* qsrc = reinterpret_cast<const float4*>(g_qsm + ((size_t)bh * TK + qc) * DD);
        for (int j = threadIdx.x; j < 128 * 16; j += 256) qs[j] = qsrc[j];
        __syncthreads();
        for (int qq = 0; qq < 128; qq++) {
            const float4* qp = qs + qq * 16;
            float a0 = 0.f, a1 = 0.f, a2 = 0.f, a3 = 0.f;
            #pragma unroll
            for (int i = 0; i < 16; i++) {
                float4 v = qp[i];
                a0 += fabsf(kr[4 * i] - v.x);
                a1 += fabsf(kr[4 * i + 1] - v.y);
                a2 += fabsf(kr[4 * i + 2] - v.z);
                a3 += fabsf(kr[4 * i + 3] - v.w);
            }
            best = fminf(best, (a0 + a1) + (a2 + a3));
        }
        __syncthreads();
    }
    g_mind[(size_t)bh * LC + kl] = best;
}

// ---------------- top-512 smallest (ties: lower index) via bitonic sort ----------------
__global__ void __launch_bounds__(1024) topk_kernel() {
    __shared__ unsigned long long keys[LC];
    int bh = blockIdx.x;
    int tid = threadIdx.x;
    for (int i = tid; i < LC; i += 1024) {
        unsigned fb = __float_as_uint(g_mind[(size_t)bh * LC + i]);  // distances >= 0
        keys[i] = ((unsigned long long)fb << 32) | (unsigned)i;
    }
    __syncthreads();
    for (int k = 2; k <= LC; k <<= 1) {
        for (int j = k >> 1; j > 0; j >>= 1) {
            for (int i = tid; i < LC; i += 1024) {
                int ixj = i ^ j;
                if (ixj > i) {
                    unsigned long long a = keys[i], b = keys[ixj];
                    bool up = ((i & k) == 0);
                    if ((a > b) == up) { keys[i] = b; keys[ixj] = a; }
                }
            }
            __syncthreads();
        }
    }
    for (int i = tid; i < TK; i += 1024)
        g_sidx[bh * TK + i] = (int)(keys[i] & 0xFFFFFFFFu);
}

// ---------------- attention: thread per q row, single-pass softmax ----------------
__global__ void __launch_bounds__(128) attn_kernel() {
    int bh = blockIdx.y;
    int b = bh >> 3, h = bh & 7;
    int ql = blockIdx.x * 128 + threadIdx.x;
    const float4* qp = reinterpret_cast<const float4*>(g_qarr + ((size_t)bh * LQ + ql) * DD);
    float qr[DD];
    #pragma unroll
    for (int i = 0; i < 16; i++) {
        float4 v = qp[i];
        qr[4 * i] = v.x; qr[4 * i + 1] = v.y; qr[4 * i + 2] = v.z; qr[4 * i + 3] = v.w;
    }
    float num[DD];
    #pragma unroll
    for (int i = 0; i < DD; i++) num[i] = 0.f;
    float den = 0.f;
    __shared__ float4 Ks[64 * 16];
    __shared__ float4 Vs[64 * 16];
    for (int kc = 0; kc < TK; kc += 64) {
        const float4* ksrc = reinterpret_cast<const float4*>(g_ksel + ((size_t)bh * TK + kc) * DD);
        const float4* vsrc = reinterpret_cast<const float4*>(g_vsel + ((size_t)bh * TK + kc) * DD);
        for (int j = threadIdx.x; j < 64 * 16; j += 128) { Ks[j] = ksrc[j]; Vs[j] = vsrc[j]; }
        __syncthreads();
        for (int kk = 0; kk < 64; kk++) {
            const float4* kp = Ks + kk * 16;
            float s0 = 0.f, s1 = 0.f, s2 = 0.f, s3 = 0.f;
            #pragma unroll
            for (int i = 0; i < 16; i++) {
                float4 v = kp[i];
                s0 += qr[4 * i] * v.x; s1 += qr[4 * i + 1] * v.y;
                s2 += qr[4 * i + 2] * v.z; s3 += qr[4 * i + 3] * v.w;
            }
            float w = __expf((s0 + s1) + (s2 + s3));  // scores in [-1,1]: no max needed
            den += w;
            const float4* vp = Vs + kk * 16;
            #pragma unroll
            for (int i = 0; i < 16; i++) {
                float4 v = vp[i];
                num[4 * i] += w * v.x; num[4 * i + 1] += w * v.y;
                num[4 * i + 2] += w * v.z; num[4 * i + 3] += w * v.w;
            }
        }
        __syncthreads();
    }
    float inv = 1.0f / den;
    float* ob = g_attnT + (size_t)b * INNER * LQ + (size_t)(h * DD) * LQ + ql;
    #pragma unroll
    for (int d = 0; d < DD; d++) ob[(size_t)d * LQ] = num[d] * inv;
}

// ---------------- host ----------------
extern "C" void kernel_launch(void* const* d_in, const int* in_sizes, int n_in,
                              void* d_out, int out_size) {
    (void)in_sizes; (void)n_in; (void)out_size;
    const float* qsrc  = (const float*)d_in[0];
    const float* ctx   = (const float*)d_in[1];
    const float* cn_g  = (const float*)d_in[2];
    const float* cn_b  = (const float*)d_in[3];
    const float* qn_g  = (const float*)d_in[4];
    const float* qn_b  = (const float*)d_in[5];
    const float* on_g  = (const float*)d_in[6];
    const float* on_b  = (const float*)d_in[7];
    const float* w_kv  = (const float*)d_in[8];
    const float* w_q   = (const float*)d_in[9];
    const float* w_out = (const float*)d_in[10];
    const float* gamma = (const float*)d_in[11];
    float* out = (float*)d_out;

    float *p_ctxn, *p_qsn, *p_kv, *p_qpr, *p_karr, *p_varr, *p_qarr, *p_attnT, *p_proj;
    cudaGetSymbolAddress((void**)&p_ctxn, g_ctxn);
    cudaGetSymbolAddress((void**)&p_qsn, g_qsn);
    cudaGetSymbolAddress((void**)&p_kv, g_kv);
    cudaGetSymbolAddress((void**)&p_qpr, g_qpr);
    cudaGetSymbolAddress((void**)&p_karr, g_karr);
    cudaGetSymbolAddress((void**)&p_varr, g_varr);
    cudaGetSymbolAddress((void**)&p_qarr, g_qarr);
    cudaGetSymbolAddress((void**)&p_attnT, g_attnT);
    cudaGetSymbolAddress((void**)&p_proj, g_proj);

    dim3 thr328(32, 8);

    // 1. ChanLN
    chan_ln_kernel<<<dim3(LC / 32, BB), thr328>>>(ctx, cn_g, cn_b, p_ctxn, CC, LC);
    chan_ln_kernel<<<dim3(LQ / 32, BB), thr328>>>(qsrc, qn_g, qn_b, p_qsn, CC, LQ);

    // 2. projections
    sgemm128<<<dim3(LC / 128, 1024 / 128, BB), 256>>>(w_kv, p_ctxn, p_kv, 1024, LC, CC,
                                                      (size_t)CC * LC, (size_t)1024 * LC);
    sgemm128<<<dim3(LQ / 128, INNER / 128, BB), 256>>>(w_q, p_qsn, p_qpr, INNER, LQ, CC,
                                                       (size_t)CC * LQ, (size_t)INNER * LQ);

    // 3. head transpose to (bh, l, d)
    head_transpose<<<dim3(LC / 32, 16, BB), thr328>>>(p_kv, p_karr, LC, (size_t)1024 * LC);
    head_transpose<<<dim3(LC / 32, 16, BB), thr328>>>(p_kv + (size_t)INNER * LC, p_varr, LC,
                                                      (size_t)1024 * LC);
    head_transpose<<<dim3(LQ / 32, 16, BB), thr328>>>(p_qpr, p_qarr, LQ, (size_t)INNER * LQ);

    // 4. L2 normalize q, k
    l2norm_rows<<<BHH * LC / 8, thr328>>>(p_karr);
    l2norm_rows<<<BHH * LQ / 8, thr328>>>(p_qarr);

    // 5. RNG + gather random Q subset
    rng_kernel<<<32, 256>>>();
    gather_qsmall<<<BHH * TK / 8, thr328>>>();

    // 6. L1 min distance + top-512 selection + gather
    l1_min_kernel<<<dim3(LC / 256, BHH), 256>>>();
    topk_kernel<<<BHH, 1024>>>();
    gather_sel<<<BHH * TK / 8, thr328>>>();

    // 7. attention
    attn_kernel<<<dim3(LQ / 128, BHH), 128>>>();

    // 8. out projection + final LN + residual
    sgemm128<<<dim3(LQ / 128, INNER / 128, BB), 256>>>(w_out, p_attnT, p_proj, INNER, LQ, CC,
                                                       (size_t)INNER * LQ, (size_t)INNER * LQ);
    final_ln_kernel<<<dim3(LQ / 32, BB), thr328>>>(p_proj, on_g, on_b, qsrc, gamma, out, CC, LQ);
}

// round 2
// speedup vs baseline: 1.0582x; 1.0582x over previous
#include <cuda_runtime.h>
#include <cstdint>

#define JAX_PARTITIONABLE 1

#define BB 2
#define CC 512
#define LQ 2048
#define LC 4096
#define HH 8
#define DD 64
#define BHH 16
#define TK 512
#define INNER 512

typedef unsigned long long ull;

// ---------------- packed f32x2 helpers (Blackwell FFMA2 path) ----------------
__device__ __forceinline__ void fma2(ull& d, ull a, ull b, ull c) {
    asm("fma.rn.f32x2 %0, %1, %2, %3;" : "=l"(d) : "l"(a), "l"(b), "l"(c));
}
__device__ __forceinline__ void add2(ull& d, ull a, ull b) {
    asm("add.rn.f32x2 %0, %1, %2;" : "=l"(d) : "l"(a), "l"(b));
}
__device__ __forceinline__ ull pack2(float x, float y) {
    ull r;
    asm("mov.b64 %0, {%1, %2};" : "=l"(r) : "r"(__float_as_uint(x)), "r"(__float_as_uint(y)));
    return r;
}
__device__ __forceinline__ float2 unpack2(ull v) {
    unsigned lo, hi;
    asm("mov.b64 {%0, %1}, %2;" : "=r"(lo), "=r"(hi) : "l"(v));
    return make_float2(__uint_as_float(lo), __uint_as_float(hi));
}

// ---------------- scratch ----------------
__device__ float g_ctxn[BB * CC * LC];
__device__ float g_qsn[BB * CC * LQ];
__device__ float g_kv[BB * 2 * INNER * LC];
__device__ float g_qpr[BB * INNER * LQ];
__device__ float g_karr[BHH * LC * DD];
__device__ float g_varr[BHH * LC * DD];
__device__ float g_qarr[BHH * LQ * DD];
__device__ float g_qsm[BHH * TK * DD];
__device__ float g_mind[BHH * LC];
__device__ int g_ridx[BHH * TK];
__device__ int g_sidx[BHH * TK];
__device__ float g_ksel[BHH * TK * DD];
__device__ float g_vsel[BHH * TK * DD];
__device__ float g_attnT[BB * INNER * LQ];
__device__ float g_proj[BB * CC * LQ];

// ---------------- Threefry-2x32 ----------------
__device__ __forceinline__ void tf2x32(unsigned k0, unsigned k1, unsigned x0,
                                       unsigned x1, unsigned& y0, unsigned& y1) {
    unsigned ks2 = k0 ^ k1 ^ 0x1BD11BDAu;
    x0 += k0; x1 += k1;
#define TFR(r) { x0 += x1; x1 = (x1 << (r)) | (x1 >> (32 - (r))); x1 ^= x0; }
    TFR(13) TFR(15) TFR(26) TFR(6)
    x0 += k1; x1 += ks2 + 1u;
    TFR(17) TFR(29) TFR(16) TFR(24)
    x0 += ks2; x1 += k0 + 2u;
    TFR(13) TFR(15) TFR(26) TFR(6)
    x0 += k0; x1 += k1 + 3u;
    TFR(17) TFR(29) TFR(16) TFR(24)
    x0 += k1; x1 += ks2 + 4u;
    TFR(13) TFR(15) TFR(26) TFR(6)
    x0 += ks2; x1 += k0 + 5u;
#undef TFR
    y0 = x0; y1 = x1;
}

__global__ void rng_kernel() {
    int i = blockIdx.x * blockDim.x + threadIdx.x;
    if (i >= BHH * TK) return;
    unsigned bits;
#if JAX_PARTITIONABLE
    unsigned k2a, k2b;
    tf2x32(0u, 42u, 0u, 1u, k2a, k2b);
    unsigned y0, y1;
    tf2x32(k2a, k2b, 0u, (unsigned)i, y0, y1);
    bits = y0 ^ y1;
#else
    unsigned a0, a1, b0, b1;
    tf2x32(0u, 42u, 0u, 2u, a0, a1);
    tf2x32(0u, 42u, 1u, 3u, b0, b1);
    unsigned k2a = a1, k2b = b1;
    int lane = (i < 4096) ? i : i - 4096;
    unsigned y0, y1;
    tf2x32(k2a, k2b, (unsigned)lane, (unsigned)(lane + 4096), y0, y1);
    bits = (i < 4096) ? y0 : y1;
#endif
    g_ridx[i] = (int)(bits & 2047u);
}

// ---------------- channel LayerNorm ----------------
__global__ void chan_ln_kernel(const float* __restrict__ x, const float* __restrict__ gw,
                               const float* __restrict__ bw, float* __restrict__ y,
                               int C, int L) {
    int b = blockIdx.y;
    int l = blockIdx.x * 32 + threadIdx.x;
    const float* xb = x + (size_t)b * C * L;
    float s = 0.f, s2 = 0.f;
    for (int c = threadIdx.y; c < C; c += 8) {
        float v = xb[(size_t)c * L + l];
        s += v; s2 += v * v;
    }
    __shared__ float sh_s[8][32], sh_s2[8][32];
    sh_s[threadIdx.y][threadIdx.x] = s;
    sh_s2[threadIdx.y][threadIdx.x] = s2;
    __syncthreads();
    if (threadIdx.y == 0) {
        float ts = 0.f, t2 = 0.f;
        #pragma unroll
        for (int i = 0; i < 8; i++) { ts += sh_s[i][threadIdx.x]; t2 += sh_s2[i][threadIdx.x]; }
        float mean = ts / (float)C;
        float var = t2 / (float)C - mean * mean;
        sh_s[0][threadIdx.x] = mean;
        sh_s2[0][threadIdx.x] = rsqrtf(var + 1e-5f);
    }
    __syncthreads();
    float mean = sh_s[0][threadIdx.x];
    float rstd = sh_s2[0][threadIdx.x];
    float* yb = y + (size_t)b * C * L;
    for (int c = threadIdx.y; c < C; c += 8) {
        float v = xb[(size_t)c * L + l];
        yb[(size_t)c * L + l] = (v - mean) * rstd * gw[c] + bw[c];
    }
}

__global__ void final_ln_kernel(const float* __restrict__ x, const float* __restrict__ gw,
                                const float* __restrict__ bw, const float* __restrict__ res,
                                const float* __restrict__ gamma, float* __restrict__ y,
                                int C, int L) {
    int b = blockIdx.y;
    int l = blockIdx.x * 32 + threadIdx.x;
    const float* xb = x + (size_t)b * C * L;
    float s = 0.f, s2 = 0.f;
    for (int c = threadIdx.y; c < C; c += 8) {
        float v = xb[(size_t)c * L + l];
        s += v; s2 += v * v;
    }
    __shared__ float sh_s[8][32], sh_s2[8][32];
    sh_s[threadIdx.y][threadIdx.x] = s;
    sh_s2[threadIdx.y][threadIdx.x] = s2;
    __syncthreads();
    if (threadIdx.y == 0) {
        float ts = 0.f, t2 = 0.f;
        #pragma unroll
        for (int i = 0; i < 8; i++) { ts += sh_s[i][threadIdx.x]; t2 += sh_s2[i][threadIdx.x]; }
        float mean = ts / (float)C;
        float var = t2 / (float)C - mean * mean;
        sh_s[0][threadIdx.x] = mean;
        sh_s2[0][threadIdx.x] = rsqrtf(var + 1e-5f);
    }
    __syncthreads();
    float mean = sh_s[0][threadIdx.x];
    float rstd = sh_s2[0][threadIdx.x];
    float gm = gamma[0];
    const float* rb = res + (size_t)b * C * L;
    float* yb = y + (size_t)b * C * L;
    for (int c = threadIdx.y; c < C; c += 8) {
        float v = xb[(size_t)c * L + l];
        yb[(size_t)c * L + l] = gm * ((v - mean) * rstd * gw[c] + bw[c]) + rb[(size_t)c * L + l];
    }
}

// ---------------- SGEMM: packed f32x2 accumulators + double-buffered smem ----------------
__global__ void __launch_bounds__(256) sgemm128(const float* __restrict__ A,
                                                const float* __restrict__ Bsrc,
                                                float* __restrict__ Csrc, int M, int N,
                                                int K, size_t bStride, size_t cStride) {
    const float* B = Bsrc + (size_t)blockIdx.z * bStride;
    float* C = Csrc + (size_t)blockIdx.z * cStride;
    int bm = blockIdx.y * 128;
    int bn = blockIdx.x * 128;
    __shared__ float As[2][8][128];
    __shared__ float Bs[2][8][128];
    int tid = threadIdx.x;
    int tx = tid & 15, ty = tid >> 4;
    ull acc2[8][4];
    #pragma unroll
    for (int i = 0; i < 8; i++)
        #pragma unroll
        for (int j = 0; j < 4; j++) acc2[i][j] = 0ull;

    int aRow = tid >> 1;
    int aCol = (tid & 1) * 4;
    int bRow = tid >> 5;
    int bCol = (tid & 31) * 4;
    const float* Aptr = A + (size_t)(bm + aRow) * K + aCol;
    const float* Bptr = B + (size_t)bRow * N + bn + bCol;

    // prologue: tile 0
    {
        float4 av = *reinterpret_cast<const float4*>(Aptr);
        float4 bv = *reinterpret_cast<const float4*>(Bptr);
        As[0][aCol + 0][aRow] = av.x; As[0][aCol + 1][aRow] = av.y;
        As[0][aCol + 2][aRow] = av.z; As[0][aCol + 3][aRow] = av.w;
        *reinterpret_cast<float4*>(&Bs[0][bRow][bCol]) = bv;
    }
    __syncthreads();

    int nt = K / 8;
    for (int t = 0; t < nt; t++) {
        int cur = t & 1;
        float4 av_n, bv_n;
        bool has_next = (t + 1 < nt);
        if (has_next) {
            av_n = *reinterpret_cast<const float4*>(Aptr + (t + 1) * 8);
            bv_n = *reinterpret_cast<const float4*>(Bptr + (size_t)(t + 1) * 8 * N);
        }
        #pragma unroll
        for (int kk = 0; kk < 8; kk++) {
            float ar[8];
            *(float4*)&ar[0] = *(float4*)&As[cur][kk][ty * 8];
            *(float4*)&ar[4] = *(float4*)&As[cur][kk][ty * 8 + 4];
            ull br2[4];
            const ull* bp = reinterpret_cast<const ull*>(&Bs[cur][kk][tx * 8]);
            br2[0] = bp[0]; br2[1] = bp[1]; br2[2] = bp[2]; br2[3] = bp[3];
            #pragma unroll
            for (int i = 0; i < 8; i++) {
                ull a2 = pack2(ar[i], ar[i]);
                #pragma unroll
                for (int j = 0; j < 4; j++) fma2(acc2[i][j], a2, br2[j], acc2[i][j]);
            }
        }
        if (has_next) {
            int nxt = cur ^ 1;
            As[nxt][aCol + 0][aRow] = av_n.x; As[nxt][aCol + 1][aRow] = av_n.y;
            As[nxt][aCol + 2][aRow] = av_n.z; As[nxt][aCol + 3][aRow] = av_n.w;
            *reinterpret_cast<float4*>(&Bs[nxt][bRow][bCol]) = bv_n;
            __syncthreads();
        }
    }
    #pragma unroll
    for (int i = 0; i < 8; i++) {
        ull* crow = reinterpret_cast<ull*>(C + (size_t)(bm + ty * 8 + i) * N + bn + tx * 8);
        crow[0] = acc2[i][0]; crow[1] = acc2[i][1];
        crow[2] = acc2[i][2]; crow[3] = acc2[i][3];
    }
}

// ---------------- head transpose ----------------
__global__ void head_transpose(const float* __restrict__ src, float* __restrict__ dst,
                               int L, size_t srcBatchStride) {
    __shared__ float tile[32][33];
    int b = blockIdx.z;
    int o0 = blockIdx.y * 32;
    int l0 = blockIdx.x * 32;
    const float* s = src + (size_t)b * srcBatchStride;
    #pragma unroll
    for (int k = 0; k < 4; k++) {
        int o = o0 + threadIdx.y + k * 8;
        tile[threadIdx.y + k * 8][threadIdx.x] = s[(size_t)o * L + l0 + threadIdx.x];
    }
    __syncthreads();
    int h = o0 >> 6;
    int dbase = o0 & 63;
    float* dph = dst + (size_t)(b * HH + h) * L * DD;
    #pragma unroll
    for (int k = 0; k < 4; k++) {
        int row = threadIdx.y + k * 8;
        int col = threadIdx.x;
        dph[(size_t)(l0 + row) * DD + dbase + col] = tile[col][row];
    }
}

// ---------------- L2 normalize rows of 64 ----------------
__global__ void l2norm_rows(float* __restrict__ x) {
    int row = blockIdx.x * 8 + threadIdx.y;
    float* p = x + (size_t)row * DD;
    int lane = threadIdx.x;
    float a = p[lane], b = p[lane + 32];
    float s = a * a + b * b;
    #pragma unroll
    for (int o = 16; o > 0; o >>= 1) s += __shfl_xor_sync(0xFFFFFFFFu, s, o);
    float n = sqrtf(s);
    float inv = 1.0f / fmaxf(n, 1e-12f);
    p[lane] = a * inv;
    p[lane + 32] = b * inv;
}

// ---------------- gathers ----------------
__global__ void gather_qsmall() {
    int r = blockIdx.x * 8 + threadIdx.y;
    int bh = r >> 9;
    int idx = g_ridx[r];
    const float* s = g_qarr + ((size_t)bh * LQ + idx) * DD;
    float* d = g_qsm + (size_t)r * DD;
    d[threadIdx.x] = s[threadIdx.x];
    d[threadIdx.x + 32] = s[threadIdx.x + 32];
}

__global__ void gather_sel() {
    int r = blockIdx.x * 8 + threadIdx.y;
    int bh = r >> 9;
    int idx = g_sidx[r];
    const float* ks = g_karr + ((size_t)bh * LC + idx) * DD;
    const float* vs = g_varr + ((size_t)bh * LC + idx) * DD;
    g_ksel[(size_t)r * DD + threadIdx.x] = ks[threadIdx.x];
    g_ksel[(size_t)r * DD + 32 + threadIdx.x] = ks[threadIdx.x + 32];
    g_vsel[(size_t)r * DD + threadIdx.x] = vs[threadIdx.x];
    g_vsel[(size_t)r * DD + 32 + threadIdx.x] = vs[threadIdx.x + 32];
}

// ---------------- L1 min-distance: packed diff/accum, abs on alu pipe ----------------
__global__ void __launch_bounds__(256, 2) l1_min_kernel() {
    int bh = blockIdx.y;
    int kl = blockIdx.x * 256 + threadIdx.x;
    const ull* kp = reinterpret_cast<const ull*>(g_karr + ((size_t)bh * LC + kl) * DD);
    ull kr2[32];
    #pragma unroll
    for (int i = 0; i < 32; i++) kr2[i] = kp[i];
    __shared__ float qs[128 * 64];  // negated q rows, 32KB
    const ull ABSM = 0x7FFFFFFF7FFFFFFFull;
    float best = 3.4e38f;
    for (int qc = 0; qc < TK; qc += 128) {
        const float4* qsrc4 = reinterpret_cast<const float4*>(g_qsm + ((size_t)bh * TK + qc) * DD);
        for (int j = threadIdx.x; j < 128 * 16; j += 256) {
            float4 v = qsrc4[j];
            reinterpret_cast<float4*>(qs)[j] = make_float4(-v.x, -v.y, -v.z, -v.w);
        }
        __syncthreads();
        for (int qq = 0; qq < 128; qq++) {
            const ull* qp = reinterpret_cast<const ull*>(qs + qq * 64);
            ull a0 = 0ull, a1 = 0ull, a2 = 0ull, a3 = 0ull;
            #pragma unroll
            for (int i = 0; i < 32; i += 4) {
                ull d0, d1, d2, d3;
                add2(d0, kr2[i + 0], qp[i + 0]); d0 &= ABSM; add2(a0, a0, d0);
                add2(d1, kr2[i + 1], qp[i + 1]); d1 &= ABSM; add2(a1, a1, d1);
                add2(d2, kr2[i + 2], qp[i + 2]); d2 &= ABSM; add2(a2, a2, d2);
                add2(d3, kr2[i + 3], qp[i + 3]); d3 &= ABSM; add2(a3, a3, d3);
            }
            ull s01, s23, s;
            add2(s01, a0, a1);
            add2(s23, a2, a3);
            add2(s, s01, s23);
            float2 f = unpack2(s);
            best = fminf(best, f.x + f.y);
        }
        __syncthreads();
    }
    g_mind[(size_t)bh * LC + kl] = best;
}

// ---------------- top-512 smallest via bitonic sort ----------------
__global__ void __launch_bounds__(1024) topk_kernel() {
    __shared__ ull keys[LC];
    int bh = blockIdx.x;
    int tid = threadIdx.x;
    for (int i = tid; i < LC; i += 1024) {
        unsigned fb = __float_as_uint(g_mind[(size_t)bh * LC + i]);
        keys[i] = ((ull)fb << 32) | (unsigned)i;
    }
    __syncthreads();
    for (int k = 2; k <= LC; k <<= 1) {
        for (int j = k >> 1; j > 0; j >>= 1) {
            for (int i = tid; i < LC; i += 1024) {
                int ixj = i ^ j;
                if (ixj > i) {
                    ull a = keys[i], b = keys[ixj];
                    bool up = ((i & k) == 0);
                    if ((a > b) == up) { keys[i] = b; keys[ixj] = a; }
                }
            }
            __syncthreads();
        }
    }
    for (int i = tid; i < TK; i += 1024)
        g_sidx[bh * TK + i] = (int)(keys[i] & 0xFFFFFFFFu);
}

// ---------------- attention: packed qk dot + packed w*v accumulate ----------------
__global__ void __launch_bounds__(128) attn_kernel() {
    int bh = blockIdx.y;
    int b = bh >> 3, h = bh & 7;
    int ql = blockIdx.x * 128 + threadIdx.x;
    const ull* qp = reinterpret_cast<const ull*>(g_qarr + ((size_t)bh * LQ + ql) * DD);
    ull qr2[32];
    #pragma unroll
    for (int i = 0; i < 32; i++) qr2[i] = qp[i];
    ull num2[32];
    #pragma unroll
    for (int i = 0; i < 32; i++) num2[i] = 0ull;
    float den = 0.f;
    __shared__ float Ks[64 * 64];
    __shared__ float Vs[64 * 64];
    for (int kc = 0; kc < TK; kc += 64) {
        const float4* ksrc = reinterpret_cast<const float4*>(g_ksel + ((size_t)bh * TK + kc) * DD);
        const float4* vsrc = reinterpret_cast<const float4*>(g_vsel + ((size_t)bh * TK + kc) * DD);
        for (int j = threadIdx.x; j < 64 * 16; j += 128) {
            reinterpret_cast<float4*>(Ks)[j] = ksrc[j];
            reinterpret_cast<float4*>(Vs)[j] = vsrc[j];
        }
        __syncthreads();
        for (int kk = 0; kk < 64; kk++) {
            const ull* kp2 = reinterpret_cast<const ull*>(Ks + kk * 64);
            ull s0 = 0ull, s1 = 0ull, s2 = 0ull, s3 = 0ull;
            #pragma unroll
            for (int i = 0; i < 32; i += 4) {
                fma2(s0, qr2[i + 0], kp2[i + 0], s0);
                fma2(s1, qr2[i + 1], kp2[i + 1], s1);
                fma2(s2, qr2[i + 2], kp2[i + 2], s2);
                fma2(s3, qr2[i + 3], kp2[i + 3], s3);
            }
            ull sA, sB, sC;
            add2(sA, s0, s1);
            add2(sB, s2, s3);
            add2(sC, sA, sB);
            float2 f = unpack2(sC);
            float w = __expf(f.x + f.y);  // scores in [-1,1]: no max-subtract needed
            den += w;
            ull w2 = pack2(w, w);
            const ull* vp2 = reinterpret_cast<const ull*>(Vs + kk * 64);
            #pragma unroll
            for (int i = 0; i < 32; i++) fma2(num2[i], w2, vp2[i], num2[i]);
        }
        __syncthreads();
    }
    float inv = 1.0f / den;
    float* ob = g_attnT + (size_t)b * INNER * LQ + (size_t)(h * DD) * LQ + ql;
    #pragma unroll
    for (int i = 0; i < 32; i++) {
        float2 f = unpack2(num2[i]);
        ob[(size_t)(2 * i) * LQ] = f.x * inv;
        ob[(size_t)(2 * i + 1) * LQ] = f.y * inv;
    }
}

// ---------------- host ----------------
extern "C" void kernel_launch(void* const* d_in, const int* in_sizes, int n_in,
                              void* d_out, int out_size) {
    (void)in_sizes; (void)n_in; (void)out_size;
    const float* qsrc  = (const float*)d_in[0];
    const float* ctx   = (const float*)d_in[1];
    const float* cn_g  = (const float*)d_in[2];
    const float* cn_b  = (const float*)d_in[3];
    const float* qn_g  = (const float*)d_in[4];
    const float* qn_b  = (const float*)d_in[5];
    const float* on_g  = (const float*)d_in[6];
    const float* on_b  = (const float*)d_in[7];
    const float* w_kv  = (const float*)d_in[8];
    const float* w_q   = (const float*)d_in[9];
    const float* w_out = (const float*)d_in[10];
    const float* gamma = (const float*)d_in[11];
    float* out = (float*)d_out;

    float *p_ctxn, *p_qsn, *p_kv, *p_qpr, *p_karr, *p_varr, *p_qarr, *p_attnT, *p_proj;
    cudaGetSymbolAddress((void**)&p_ctxn, g_ctxn);
    cudaGetSymbolAddress((void**)&p_qsn, g_qsn);
    cudaGetSymbolAddress((void**)&p_kv, g_kv);
    cudaGetSymbolAddress((void**)&p_qpr, g_qpr);
    cudaGetSymbolAddress((void**)&p_karr, g_karr);
    cudaGetSymbolAddress((void**)&p_varr, g_varr);
    cudaGetSymbolAddress((void**)&p_qarr, g_qarr);
    cudaGetSymbolAddress((void**)&p_attnT, g_attnT);
    cudaGetSymbolAddress((void**)&p_proj, g_proj);

    dim3 thr328(32, 8);

    chan_ln_kernel<<<dim3(LC / 32, BB), thr328>>>(ctx, cn_g, cn_b, p_ctxn, CC, LC);
    chan_ln_kernel<<<dim3(LQ / 32, BB), thr328>>>(qsrc, qn_g, qn_b, p_qsn, CC, LQ);

    sgemm128<<<dim3(LC / 128, 1024 / 128, BB), 256>>>(w_kv, p_ctxn, p_kv, 1024, LC, CC,
                                                      (size_t)CC * LC, (size_t)1024 * LC);
    sgemm128<<<dim3(LQ / 128, INNER / 128, BB), 256>>>(w_q, p_qsn, p_qpr, INNER, LQ, CC,
                                                       (size_t)CC * LQ, (size_t)INNER * LQ);

    head_transpose<<<dim3(LC / 32, 16, BB), thr328>>>(p_kv, p_karr, LC, (size_t)1024 * LC);
    head_transpose<<<dim3(LC / 32, 16, BB), thr328>>>(p_kv + (size_t)INNER * LC, p_varr, LC,
                                                      (size_t)1024 * LC);
    head_transpose<<<dim3(LQ / 32, 16, BB), thr328>>>(p_qpr, p_qarr, LQ, (size_t)INNER * LQ);

    l2norm_rows<<<BHH * LC / 8, thr328>>>(p_karr);
    l2norm_rows<<<BHH * LQ / 8, thr328>>>(p_qarr);

    rng_kernel<<<32, 256>>>();
    gather_qsmall<<<BHH * TK / 8, thr328>>>();

    l1_min_kernel<<<dim3(LC / 256, BHH), 256>>>();
    topk_kernel<<<BHH, 1024>>>();
    gather_sel<<<BHH * TK / 8, thr328>>>();

    attn_kernel<<<dim3(LQ / 128, BHH), 128>>>();

    sgemm128<<<dim3(LQ / 128, INNER / 128, BB), 256>>>(w_out, p_attnT, p_proj, INNER, LQ, CC,
                                                       (size_t)INNER * LQ, (size_t)INNER * LQ);
    final_ln_kernel<<<dim3(LQ / 32, BB), thr328>>>(p_proj, on_g, on_b, qsrc, gamma, out, CC, LQ);
}

// round 4
// speedup vs baseline: 1.0631x; 1.0046x over previous
#include <cuda_runtime.h>
#include <cstdint>

#define JAX_PARTITIONABLE 1

#define BB 2
#define CC 512
#define LQ 2048
#define LC 4096
#define HH 8
#define DD 64
#define BHH 16
#define TK 512
#define INNER 512

typedef unsigned long long ull;

// ---------------- packed f32x2 helpers ----------------
__device__ __forceinline__ void fma2(ull& d, ull a, ull b, ull c) {
    asm("fma.rn.f32x2 %0, %1, %2, %3;" : "=l"(d) : "l"(a), "l"(b), "l"(c));
}
__device__ __forceinline__ void add2(ull& d, ull a, ull b) {
    asm("add.rn.f32x2 %0, %1, %2;" : "=l"(d) : "l"(a), "l"(b));
}
__device__ __forceinline__ ull pack2(float x, float y) {
    ull r;
    asm("mov.b64 %0, {%1, %2};" : "=l"(r) : "r"(__float_as_uint(x)), "r"(__float_as_uint(y)));
    return r;
}
__device__ __forceinline__ float2 unpack2(ull v) {
    unsigned lo, hi;
    asm("mov.b64 {%0, %1}, %2;" : "=r"(lo), "=r"(hi) : "l"(v));
    return make_float2(__uint_as_float(lo), __uint_as_float(hi));
}

// ---------------- tf32 mma helpers (legacy HMMA path, works on base sm_100) ----------------
__device__ __forceinline__ uint32_t f2tf32(float x) {
    uint32_t r;
    asm("cvt.rna.tf32.f32 %0, %1;" : "=r"(r) : "f"(x));
    return r;
}
__device__ __forceinline__ void mma_tf32(float* c, const uint32_t* a, const uint32_t* b) {
    asm volatile(
        "mma.sync.aligned.m16n8k8.row.col.f32.tf32.tf32.f32 "
        "{%0,%1,%2,%3}, {%4,%5,%6,%7}, {%8,%9}, {%0,%1,%2,%3};"
        : "+f"(c[0]), "+f"(c[1]), "+f"(c[2]), "+f"(c[3])
        : "r"(a[0]), "r"(a[1]), "r"(a[2]), "r"(a[3]), "r"(b[0]), "r"(b[1]));
}

// ---------------- scratch ----------------
__device__ float g_ctxT[BB * LC * CC];        // (b, l, c)
__device__ float g_qsT[BB * LQ * CC];         // (b, l, c)
__device__ float g_dkv[BB * LC * 2 * INNER];  // (b, l, o) o<512 k, o>=512 v
__device__ float g_dq[BB * LQ * INNER];       // (b, l, o)
__device__ float g_attnO[BB * LQ * INNER];    // (b, l, o)
__device__ float g_dout[BB * LQ * CC];        // (b, l, c)
__device__ float g_qsm[BHH * TK * DD];
__device__ float g_mind[BHH * LC];
__device__ int g_ridx[BHH * TK];
__device__ int g_sidx[BHH * TK];
__device__ float g_ksel[BHH * TK * DD];
__device__ float g_vsel[BHH * TK * DD];

// ---------------- Threefry ----------------
__device__ __forceinline__ void tf2x32(unsigned k0, unsigned k1, unsigned x0,
                                       unsigned x1, unsigned& y0, unsigned& y1) {
    unsigned ks2 = k0 ^ k1 ^ 0x1BD11BDAu;
    x0 += k0; x1 += k1;
#define TFR(r) { x0 += x1; x1 = (x1 << (r)) | (x1 >> (32 - (r))); x1 ^= x0; }
    TFR(13) TFR(15) TFR(26) TFR(6)
    x0 += k1; x1 += ks2 + 1u;
    TFR(17) TFR(29) TFR(16) TFR(24)
    x0 += ks2; x1 += k0 + 2u;
    TFR(13) TFR(15) TFR(26) TFR(6)
    x0 += k0; x1 += k1 + 3u;
    TFR(17) TFR(29) TFR(16) TFR(24)
    x0 += k1; x1 += ks2 + 4u;
    TFR(13) TFR(15) TFR(26) TFR(6)
    x0 += ks2; x1 += k0 + 5u;
#undef TFR
    y0 = x0; y1 = x1;
}

__global__ void rng_kernel() {
    int i = blockIdx.x * blockDim.x + threadIdx.x;
    if (i >= BHH * TK) return;
    unsigned bits;
#if JAX_PARTITIONABLE
    unsigned k2a, k2b;
    tf2x32(0u, 42u, 0u, 1u, k2a, k2b);
    unsigned y0, y1;
    tf2x32(k2a, k2b, 0u, (unsigned)i, y0, y1);
    bits = y0 ^ y1;
#else
    unsigned a0, a1, b0, b1;
    tf2x32(0u, 42u, 0u, 2u, a0, a1);
    tf2x32(0u, 42u, 1u, 3u, b0, b1);
    int lane = (i < 4096) ? i : i - 4096;
    unsigned y0, y1;
    tf2x32(a1, b1, (unsigned)lane, (unsigned)(lane + 4096), y0, y1);
    bits = (i < 4096) ? y0 : y1;
#endif
    g_ridx[i] = (int)(bits & 2047u);
}

// ---------------- ChanLN with transposed output: x (b,C,L) -> y (b,L,C) ----------------
__global__ void chan_ln_t(const float* __restrict__ x, const float* __restrict__ gw,
                          const float* __restrict__ bw, float* __restrict__ y, int L) {
    int b = blockIdx.y;
    int l0 = blockIdx.x * 32;
    int lane = threadIdx.x, wy = threadIdx.y;
    const float* xb = x + (size_t)b * CC * L;
    float s = 0.f, s2 = 0.f;
    for (int c = wy; c < CC; c += 8) {
        float v = xb[(size_t)c * L + l0 + lane];
        s += v; s2 += v * v;
    }
    __shared__ float sh_s[8][32], sh_s2[8][32];
    __shared__ float mean_s[32], rstd_s[32];
    __shared__ float tile[32][33];
    sh_s[wy][lane] = s; sh_s2[wy][lane] = s2;
    __syncthreads();
    if (wy == 0) {
        float ts = 0.f, t2 = 0.f;
        #pragma unroll
        for (int i = 0; i < 8; i++) { ts += sh_s[i][lane]; t2 += sh_s2[i][lane]; }
        float mean = ts / (float)CC;
        float var = t2 / (float)CC - mean * mean;
        mean_s[lane] = mean;
        rstd_s[lane] = rsqrtf(var + 1e-5f);
    }
    __syncthreads();
    float* yb = y + (size_t)b * L * CC;
    for (int c0 = 0; c0 < CC; c0 += 32) {
        #pragma unroll
        for (int rr = 0; rr < 4; rr++) {
            int cr = wy * 4 + rr;
            tile[cr][lane] = xb[(size_t)(c0 + cr) * L + l0 + lane];
        }
        __syncthreads();
        #pragma unroll
        for (int rr = 0; rr < 4; rr++) {
            int r = wy * 4 + rr;     // l offset
            int c = c0 + lane;       // channel
            float v = tile[lane][r];
            yb[(size_t)(l0 + r) * CC + c] = (v - mean_s[r]) * rstd_s[r] * gw[c] + bw[c];
        }
        __syncthreads();
    }
}

// ---------------- final LN: x (b,L,512) -> out (b,512,L), + gamma*.. + residual ----------------
__global__ void final_ln_t(const float* __restrict__ x, const float* __restrict__ gw,
                           const float* __restrict__ bw, const float* __restrict__ res,
                           const float* __restrict__ gamma, float* __restrict__ y) {
    int b = blockIdx.y;
    int l0 = blockIdx.x * 32;
    int lane = threadIdx.x, wy = threadIdx.y;
    const float* xb = x + (size_t)b * LQ * CC;
    __shared__ float mean_s[32], rstd_s[32];
    __shared__ float tile[32][33];
    #pragma unroll
    for (int rr = 0; rr < 4; rr++) {
        int r = wy * 4 + rr;
        const float* row = xb + (size_t)(l0 + r) * CC;
        float s = 0.f, s2 = 0.f;
        for (int c = lane; c < CC; c += 32) { float v = row[c]; s += v; s2 += v * v; }
        #pragma unroll
        for (int o = 16; o > 0; o >>= 1) {
            s += __shfl_xor_sync(0xFFFFFFFFu, s, o);
            s2 += __shfl_xor_sync(0xFFFFFFFFu, s2, o);
        }
        if (lane == 0) {
            float mean = s / (float)CC;
            float var = s2 / (float)CC - mean * mean;
            mean_s[r] = mean;
            rstd_s[r] = rsqrtf(var + 1e-5f);
        }
    }
    __syncthreads();
    float gm = gamma[0];
    const float* rb = res + (size_t)b * CC * LQ;
    float* yb = y + (size_t)b * CC * LQ;
    for (int c0 = 0; c0 < CC; c0 += 32) {
        #pragma unroll
        for (int rr = 0; rr < 4; rr++) {
            int r = wy * 4 + rr;
            tile[r][lane] = xb[(size_t)(l0 + r) * CC + c0 + lane];
        }
        __syncthreads();
        #pragma unroll
        for (int rr = 0; rr < 4; rr++) {
            int cr = wy * 4 + rr;
            int c = c0 + cr;
            float v = tile[lane][cr];
            float o = gm * ((v - mean_s[lane]) * rstd_s[lane] * gw[c] + bw[c])
                      + rb[(size_t)c * LQ + l0 + lane];
            yb[(size_t)c * LQ + l0 + lane] = o;
        }
        __syncthreads();
    }
}

// ---------------- 3xTF32 mma.sync GEMM: D[l][o] = sum_c X[l][c] * W[o][c] ----------------
// X: (M x 512) batched rows, W: (Ncols x 512), D: (M x Ncols) batched.
// CTA tile 128x128, 256 threads = 8 warps (2m x 4n), warp tile 64x32, k-chunk 16.
#define KC 16
#define LDPAD 20
__global__ void __launch_bounds__(256, 2) mma3_gemm(const float* __restrict__ X,
                                                    const float* __restrict__ W,
                                                    float* __restrict__ Dout, int Ncols,
                                                    size_t xStride, size_t dStride) {
    __shared__ uint32_t Ah[128 * LDPAD], Al[128 * LDPAD];
    __shared__ uint32_t Bh[128 * LDPAD], Bl[128 * LDPAD];
    int tid = threadIdx.x;
    int warp = tid >> 5, lane = tid & 31;
    int wm = warp & 1, wn = warp >> 1;
    int g = lane >> 2, t = lane & 3;
    int bn = blockIdx.x * 128, bm = blockIdx.y * 128, b = blockIdx.z;
    const float* Xb = X + (size_t)b * xStride;
    float* Db = Dout + (size_t)b * dStride;

    float acc[4][4][4];
    #pragma unroll
    for (int i = 0; i < 4; i++)
        #pragma unroll
        for (int j = 0; j < 4; j++)
            #pragma unroll
            for (int e = 0; e < 4; e++) acc[i][j][e] = 0.f;

    int ldrow = tid >> 1;
    int ldc = (tid & 1) * 8;
    const float* xp = Xb + (size_t)(bm + ldrow) * CC + ldc;
    const float* wp = W + (size_t)(bn + ldrow) * CC + ldc;

    for (int kc = 0; kc < CC; kc += KC) {
        // load + hi/lo split
        float va[8], vb[8];
        *(float4*)&va[0] = *reinterpret_cast<const float4*>(xp + kc);
        *(float4*)&va[4] = *reinterpret_cast<const float4*>(xp + kc + 4);
        *(float4*)&vb[0] = *reinterpret_cast<const float4*>(wp + kc);
        *(float4*)&vb[4] = *reinterpret_cast<const float4*>(wp + kc + 4);
        #pragma unroll
        for (int e = 0; e < 8; e++) {
            uint32_t h = f2tf32(va[e]);
            Ah[ldrow * LDPAD + ldc + e] = h;
            Al[ldrow * LDPAD + ldc + e] = f2tf32(va[e] - __uint_as_float(h));
            uint32_t hb = f2tf32(vb[e]);
            Bh[ldrow * LDPAD + ldc + e] = hb;
            Bl[ldrow * LDPAD + ldc + e] = f2tf32(vb[e] - __uint_as_float(hb));
        }
        __syncthreads();
        #pragma unroll
        for (int ks = 0; ks < 2; ks++) {
            int kk = ks * 8 + t;
            uint32_t ahi[4][4], alo[4][4];
            #pragma unroll
            for (int mt = 0; mt < 4; mt++) {
                int r = (wm * 64 + mt * 16 + g) * LDPAD + kk;
                ahi[mt][0] = Ah[r];
                ahi[mt][1] = Ah[r + 8 * LDPAD];
                ahi[mt][2] = Ah[r + 4];
                ahi[mt][3] = Ah[r + 8 * LDPAD + 4];
                alo[mt][0] = Al[r];
                alo[mt][1] = Al[r + 8 * LDPAD];
                alo[mt][2] = Al[r + 4];
                alo[mt][3] = Al[r + 8 * LDPAD + 4];
            }
            #pragma unroll
            for (int nt = 0; nt < 4; nt++) {
                int nb = (wn * 32 + nt * 8 + g) * LDPAD + kk;
                uint32_t bhi[2], blo[2];
                bhi[0] = Bh[nb]; bhi[1] = Bh[nb + 4];
                blo[0] = Bl[nb]; blo[1] = Bl[nb + 4];
                #pragma unroll
                for (int mt = 0; mt < 4; mt++) {
                    mma_tf32(acc[mt][nt], ahi[mt], bhi);
                    mma_tf32(acc[mt][nt], ahi[mt], blo);
                    mma_tf32(acc[mt][nt], alo[mt], bhi);
                }
            }
        }
        __syncthreads();
    }
    // epilogue
    #pragma unroll
    for (int mt = 0; mt < 4; mt++) {
        int r0 = bm + wm * 64 + mt * 16 + g;
        #pragma unroll
        for (int nt = 0; nt < 4; nt++) {
            int c0 = bn + wn * 32 + nt * 8 + t * 2;
            *reinterpret_cast<float2*>(&Db[(size_t)r0 * Ncols + c0]) =
                make_float2(acc[mt][nt][0], acc[mt][nt][1]);
            *reinterpret_cast<float2*>(&Db[(size_t)(r0 + 8) * Ncols + c0]) =
                make_float2(acc[mt][nt][2], acc[mt][nt][3]);
        }
    }
}

// ---------------- L2 normalize groups of 64 within rows ----------------
__global__ void l2norm_groups(float* __restrict__ x, int rowStride) {
    int row = blockIdx.x;
    int h = threadIdx.y, lane = threadIdx.x;
    float* p = x + (size_t)row * rowStride + h * DD;
    float a = p[lane], b = p[lane + 32];
    float s = a * a + b * b;
    #pragma unroll
    for (int o = 16; o > 0; o >>= 1) s += __shfl_xor_sync(0xFFFFFFFFu, s, o);
    float inv = 1.0f / fmaxf(sqrtf(s), 1e-12f);
    p[lane] = a * inv;
    p[lane + 32] = b * inv;
}

// ---------------- gathers ----------------
__global__ void gather_qsmall() {
    int r = blockIdx.x * 8 + threadIdx.y;
    int bh = r >> 9;
    int b = bh >> 3, h = bh & 7;
    int idx = g_ridx[r];
    const float* s = g_dq + ((size_t)b * LQ + idx) * INNER + h * DD;
    float* d = g_qsm + (size_t)r * DD;
    d[threadIdx.x] = s[threadIdx.x];
    d[threadIdx.x + 32] = s[threadIdx.x + 32];
}

__global__ void gather_sel() {
    int r = blockIdx.x * 8 + threadIdx.y;
    int bh = r >> 9;
    int b = bh >> 3, h = bh & 7;
    int idx = g_sidx[r];
    const float* ks = g_dkv + ((size_t)b * LC + idx) * (2 * INNER) + h * DD;
    g_ksel[(size_t)r * DD + threadIdx.x] = ks[threadIdx.x];
    g_ksel[(size_t)r * DD + 32 + threadIdx.x] = ks[threadIdx.x + 32];
    g_vsel[(size_t)r * DD + threadIdx.x] = ks[INNER + threadIdx.x];
    g_vsel[(size_t)r * DD + 32 + threadIdx.x] = ks[INNER + threadIdx.x + 32];
}

// ---------------- L1 min-distance ----------------
__global__ void __launch_bounds__(256, 2) l1_min_kernel() {
    int bh = blockIdx.y;
    int b = bh >> 3, h = bh & 7;
    int kl = blockIdx.x * 256 + threadIdx.x;
    const ull* kp = reinterpret_cast<const ull*>(g_dkv + ((size_t)b * LC + kl) * (2 * INNER) + h * DD);
    ull kr2[32];
    #pragma unroll
    for (int i = 0; i < 32; i++) kr2[i] = kp[i];
    __shared__ float qs[128 * 64];
    const ull ABSM = 0x7FFFFFFF7FFFFFFFull;
    float best = 3.4e38f;
    for (int qc = 0; qc < TK; qc += 128) {
        const float4* qsrc4 = reinterpret_cast<const float4*>(g_qsm + ((size_t)bh * TK + qc) * DD);
        for (int j = threadIdx.x; j < 128 * 16; j += 256) {
            float4 v = qsrc4[j];
            reinterpret_cast<float4*>(qs)[j] = make_float4(-v.x, -v.y, -v.z, -v.w);
        }
        __syncthreads();
        for (int qq = 0; qq < 128; qq++) {
            const ull* qp = reinterpret_cast<const ull*>(qs + qq * 64);
            ull a0 = 0ull, a1 = 0ull, a2 = 0ull, a3 = 0ull;
            #pragma unroll
            for (int i = 0; i < 32; i += 4) {
                ull d0, d1, d2, d3;
                add2(d0, kr2[i + 0], qp[i + 0]); d0 &= ABSM; add2(a0, a0, d0);
                add2(d1, kr2[i + 1], qp[i + 1]); d1 &= ABSM; add2(a1, a1, d1);
                add2(d2, kr2[i + 2], qp[i + 2]); d2 &= ABSM; add2(a2, a2, d2);
                add2(d3, kr2[i + 3], qp[i + 3]); d3 &= ABSM; add2(a3, a3, d3);
            }
            ull s01, s23, s;
            add2(s01, a0, a1);
            add2(s23, a2, a3);
            add2(s, s01, s23);
            float2 f = unpack2(s);
            best = fminf(best, f.x + f.y);
        }
        __syncthreads();
    }
    g_mind[(size_t)bh * LC + kl] = best;
}

// ---------------- top-512 smallest via bitonic sort ----------------
__global__ void __launch_bounds__(1024) topk_kernel() {
    __shared__ ull keys[LC];
    int bh = blockIdx.x;
    int tid = threadIdx.x;
    for (int i = tid; i < LC; i += 1024) {
        unsigned fb = __float_as_uint(g_mind[(size_t)bh * LC + i]);
        keys[i] = ((ull)fb << 32) | (unsigned)i;
    }
    __syncthreads();
    for (int k = 2; k <= LC; k <<= 1) {
        for (int j = k >> 1; j > 0; j >>= 1) {
            for (int i = tid; i < LC; i += 1024) {
                int ixj = i ^ j;
                if (ixj > i) {
                    ull a = keys[i], bb = keys[ixj];
                    bool up = ((i & k) == 0);
                    if ((a > bb) == up) { keys[i] = bb; keys[ixj] = a; }
                }
            }
            __syncthreads();
        }
    }
    for (int i = tid; i < TK; i += 1024)
        g_sidx[bh * TK + i] = (int)(keys[i] & 0xFFFFFFFFu);
}

// ---------------- attention ----------------
__global__ void __launch_bounds__(128) attn_kernel() {
    int bh = blockIdx.y;
    int b = bh >> 3, h = bh & 7;
    int ql = blockIdx.x * 128 + threadIdx.x;
    const ull* qp = reinterpret_cast<const ull*>(g_dq + ((size_t)b * LQ + ql) * INNER + h * DD);
    ull qr2[32];
    #pragma unroll
    for (int i = 0; i < 32; i++) qr2[i] = qp[i];
    ull num2[32];
    #pragma unroll
    for (int i = 0; i < 32; i++) num2[i] = 0ull;
    float den = 0.f;
    __shared__ float Ks[64 * 64];
    __shared__ float Vs[64 * 64];
    for (int kc = 0; kc < TK; kc += 64) {
        const float4* ksrc = reinterpret_cast<const float4*>(g_ksel + ((size_t)bh * TK + kc) * DD);
        const float4* vsrc = reinterpret_cast<const float4*>(g_vsel + ((size_t)bh * TK + kc) * DD);
        for (int j = threadIdx.x; j < 64 * 16; j += 128) {
            reinterpret_cast<float4*>(Ks)[j] = ksrc[j];
            reinterpret_cast<float4*>(Vs)[j] = vsrc[j];
        }
        __syncthreads();
        for (int kk = 0; kk < 64; kk++) {
            const ull* kp2 = reinterpret_cast<const ull*>(Ks + kk * 64);
            ull s0 = 0ull, s1 = 0ull, s2 = 0ull, s3 = 0ull;
            #pragma unroll
            for (int i = 0; i < 32; i += 4) {
                fma2(s0, qr2[i + 0], kp2[i + 0], s0);
                fma2(s1, qr2[i + 1], kp2[i + 1], s1);
                fma2(s2, qr2[i + 2], kp2[i + 2], s2);
                fma2(s3, qr2[i + 3], kp2[i + 3], s3);
            }
            ull sA, sB, sC;
            add2(sA, s0, s1);
            add2(sB, s2, s3);
            add2(sC, sA, sB);
            float2 f = unpack2(sC);
            float w = __expf(f.x + f.y);
            den += w;
            ull w2 = pack2(w, w);
            const ull* vp2 = reinterpret_cast<const ull*>(Vs + kk * 64);
            #pragma unroll
            for (int i = 0; i < 32; i++) fma2(num2[i], w2, vp2[i], num2[i]);
        }
        __syncthreads();
    }
    float inv = 1.0f / den;
    float* ob = g_attnO + ((size_t)b * LQ + ql) * INNER + h * DD;
    #pragma unroll
    for (int i = 0; i < 32; i++) {
        float2 f = unpack2(num2[i]);
        ob[2 * i] = f.x * inv;
        ob[2 * i + 1] = f.y * inv;
    }
}

// ---------------- host ----------------
extern "C" void kernel_launch(void* const* d_in, const int* in_sizes, int n_in,
                              void* d_out, int out_size) {
    (void)in_sizes; (void)n_in; (void)out_size;
    const float* qsrc  = (const float*)d_in[0];
    const float* ctx   = (const float*)d_in[1];
    const float* cn_g  = (const float*)d_in[2];
    const float* cn_b  = (const float*)d_in[3];
    const float* qn_g  = (const float*)d_in[4];
    const float* qn_b  = (const float*)d_in[5];
    const float* on_g  = (const float*)d_in[6];
    const float* on_b  = (const float*)d_in[7];
    const float* w_kv  = (const float*)d_in[8];
    const float* w_q   = (const float*)d_in[9];
    const float* w_out = (const float*)d_in[10];
    const float* gamma = (const float*)d_in[11];
    float* out = (float*)d_out;

    float *p_ctxT, *p_qsT, *p_dkv, *p_dq, *p_attnO, *p_dout;
    cudaGetSymbolAddress((void**)&p_ctxT, g_ctxT);
    cudaGetSymbolAddress((void**)&p_qsT, g_qsT);
    cudaGetSymbolAddress((void**)&p_dkv, g_dkv);
    cudaGetSymbolAddress((void**)&p_dq, g_dq);
    cudaGetSymbolAddress((void**)&p_attnO, g_attnO);
    cudaGetSymbolAddress((void**)&p_dout, g_dout);

    dim3 thr328(32, 8);

    chan_ln_t<<<dim3(LC / 32, BB), thr328>>>(ctx, cn_g, cn_b, p_ctxT, LC);
    chan_ln_t<<<dim3(LQ / 32, BB), thr328>>>(qsrc, qn_g, qn_b, p_qsT, LQ);

    mma3_gemm<<<dim3(1024 / 128, LC / 128, BB), 256>>>(p_ctxT, w_kv, p_dkv, 1024,
                                                       (size_t)LC * CC, (size_t)LC * 1024);
    mma3_gemm<<<dim3(INNER / 128, LQ / 128, BB), 256>>>(p_qsT, w_q, p_dq, INNER,
                                                        (size_t)LQ * CC, (size_t)LQ * INNER);

    l2norm_groups<<<BB * LC, thr328>>>(p_dkv, 2 * INNER);
    l2norm_groups<<<BB * LQ, thr328>>>(p_dq, INNER);

    rng_kernel<<<32, 256>>>();
    gather_qsmall<<<BHH * TK / 8, thr328>>>();

    l1_min_kernel<<<dim3(LC / 256, BHH), 256>>>();
    topk_kernel<<<BHH, 1024>>>();
    gather_sel<<<BHH * TK / 8, thr328>>>();

    attn_kernel<<<dim3(LQ / 128, BHH), 128>>>();

    mma3_gemm<<<dim3(INNER / 128, LQ / 128, BB), 256>>>(p_attnO, w_out, p_dout, INNER,
                                                        (size_t)LQ * INNER, (size_t)LQ * INNER);
    final_ln_t<<<dim3(LQ / 32, BB), thr328>>>(p_dout, on_g, on_b, qsrc, gamma, out);
}

// round 5
// speedup vs baseline: 1.1597x; 1.0908x over previous
#include <cuda_runtime.h>
#include <cstdint>

#define JAX_PARTITIONABLE 1

#define BB 2
#define CC 512
#define LQ 2048
#define LC 4096
#define HH 8
#define DD 64
#define BHH 16
#define TK 512
#define INNER 512

typedef unsigned long long ull;

// ---------------- packed f32x2 helpers ----------------
__device__ __forceinline__ void fma2(ull& d, ull a, ull b, ull c) {
    asm("fma.rn.f32x2 %0, %1, %2, %3;" : "=l"(d) : "l"(a), "l"(b), "l"(c));
}
__device__ __forceinline__ void add2(ull& d, ull a, ull b) {
    asm("add.rn.f32x2 %0, %1, %2;" : "=l"(d) : "l"(a), "l"(b));
}
__device__ __forceinline__ ull pack2(float x, float y) {
    ull r;
    asm("mov.b64 %0, {%1, %2};" : "=l"(r) : "r"(__float_as_uint(x)), "r"(__float_as_uint(y)));
    return r;
}
__device__ __forceinline__ float2 unpack2(ull v) {
    unsigned lo, hi;
    asm("mov.b64 {%0, %1}, %2;" : "=r"(lo), "=r"(hi) : "l"(v));
    return make_float2(__uint_as_float(lo), __uint_as_float(hi));
}

// ---------------- tf32 helpers ----------------
__device__ __forceinline__ uint32_t f2tf32(float x) {
    uint32_t r;
    asm("cvt.rna.tf32.f32 %0, %1;" : "=r"(r) : "f"(x));
    return r;
}
__device__ __forceinline__ void mma_tf32(float* c, const uint32_t* a, const uint32_t* b) {
    asm volatile(
        "mma.sync.aligned.m16n8k8.row.col.f32.tf32.tf32.f32 "
        "{%0,%1,%2,%3}, {%4,%5,%6,%7}, {%8,%9}, {%0,%1,%2,%3};"
        : "+f"(c[0]), "+f"(c[1]), "+f"(c[2]), "+f"(c[3])
        : "r"(a[0]), "r"(a[1]), "r"(a[2]), "r"(a[3]), "r"(b[0]), "r"(b[1]));
}
__device__ __forceinline__ uint32_t smem_u32(const void* p) {
    uint32_t a;
    asm("{ .reg .u64 t; cvta.to.shared.u64 t, %1; cvt.u32.u64 %0, t; }" : "=r"(a) : "l"(p));
    return a;
}
__device__ __forceinline__ void cpa16(uint32_t s, const void* g) {
    asm volatile("cp.async.cg.shared.global [%0], [%1], 16;" :: "r"(s), "l"(g));
}

// ---------------- scratch ----------------
__device__ uint32_t g_ctxh[BB * LC * CC];  // tf32-hi of LN(context), (b,l,c)
__device__ uint32_t g_ctxl[BB * LC * CC];
__device__ uint32_t g_qsh[BB * LQ * CC];
__device__ uint32_t g_qsl[BB * LQ * CC];
__device__ uint32_t g_wkvh[1024 * CC];
__device__ uint32_t g_wkvl[1024 * CC];
__device__ uint32_t g_wqh[INNER * CC];
__device__ uint32_t g_wql[INNER * CC];
__device__ uint32_t g_woh[CC * INNER];
__device__ uint32_t g_wol[CC * INNER];
__device__ uint32_t g_aoh[BB * LQ * INNER];  // attn out hi/lo, (b,l,o)
__device__ uint32_t g_aol[BB * LQ * INNER];
__device__ float g_dkv[BB * LC * 2 * INNER];  // (b, l, o)
__device__ float g_dq[BB * LQ * INNER];
__device__ float g_dout[BB * LQ * CC];
__device__ float g_qsm[BHH * TK * DD];
__device__ float g_mind[BHH * LC];
__device__ int g_ridx[BHH * TK];
__device__ int g_sidx[BHH * TK];
__device__ float g_ksel[BHH * TK * DD];
__device__ float g_vsel[BHH * TK * DD];

// ---------------- Threefry ----------------
__device__ __forceinline__ void tf2x32(unsigned k0, unsigned k1, unsigned x0,
                                       unsigned x1, unsigned& y0, unsigned& y1) {
    unsigned ks2 = k0 ^ k1 ^ 0x1BD11BDAu;
    x0 += k0; x1 += k1;
#define TFR(r) { x0 += x1; x1 = (x1 << (r)) | (x1 >> (32 - (r))); x1 ^= x0; }
    TFR(13) TFR(15) TFR(26) TFR(6)
    x0 += k1; x1 += ks2 + 1u;
    TFR(17) TFR(29) TFR(16) TFR(24)
    x0 += ks2; x1 += k0 + 2u;
    TFR(13) TFR(15) TFR(26) TFR(6)
    x0 += k0; x1 += k1 + 3u;
    TFR(17) TFR(29) TFR(16) TFR(24)
    x0 += k1; x1 += ks2 + 4u;
    TFR(13) TFR(15) TFR(26) TFR(6)
    x0 += ks2; x1 += k0 + 5u;
#undef TFR
    y0 = x0; y1 = x1;
}

__global__ void rng_kernel() {
    int i = blockIdx.x * blockDim.x + threadIdx.x;
    if (i >= BHH * TK) return;
    unsigned bits;
#if JAX_PARTITIONABLE
    unsigned k2a, k2b;
    tf2x32(0u, 42u, 0u, 1u, k2a, k2b);
    unsigned y0, y1;
    tf2x32(k2a, k2b, 0u, (unsigned)i, y0, y1);
    bits = y0 ^ y1;
#else
    unsigned a0, a1, b0, b1;
    tf2x32(0u, 42u, 0u, 2u, a0, a1);
    tf2x32(0u, 42u, 1u, 3u, b0, b1);
    int lane = (i < 4096) ? i : i - 4096;
    unsigned y0, y1;
    tf2x32(a1, b1, (unsigned)lane, (unsigned)(lane + 4096), y0, y1);
    bits = (i < 4096) ? y0 : y1;
#endif
    g_ridx[i] = (int)(bits & 2047u);
}

// ---------------- weight hi/lo split ----------------
__global__ void split_kernel(const float* __restrict__ src, uint32_t* __restrict__ hi,
                             uint32_t* __restrict__ lo, int n) {
    int i = blockIdx.x * 256 + threadIdx.x;
    if (i >= n) return;
    float x = src[i];
    uint32_t h = f2tf32(x);
    hi[i] = h;
    lo[i] = f2tf32(x - __uint_as_float(h));
}

// ---------------- ChanLN: x (b,C,L) -> tf32 hi/lo (b,L,C) ----------------
__global__ void chan_ln_t(const float* __restrict__ x, const float* __restrict__ gw,
                          const float* __restrict__ bw, uint32_t* __restrict__ yh,
                          uint32_t* __restrict__ yl, int L) {
    int b = blockIdx.y;
    int l0 = blockIdx.x * 32;
    int lane = threadIdx.x, wy = threadIdx.y;
    const float* xb = x + (size_t)b * CC * L;
    float s = 0.f, s2 = 0.f;
    for (int c = wy; c < CC; c += 8) {
        float v = xb[(size_t)c * L + l0 + lane];
        s += v; s2 += v * v;
    }
    __shared__ float sh_s[8][32], sh_s2[8][32];
    __shared__ float mean_s[32], rstd_s[32];
    __shared__ float tile[32][33];
    sh_s[wy][lane] = s; sh_s2[wy][lane] = s2;
    __syncthreads();
    if (wy == 0) {
        float ts = 0.f, t2 = 0.f;
        #pragma unroll
        for (int i = 0; i < 8; i++) { ts += sh_s[i][lane]; t2 += sh_s2[i][lane]; }
        float mean = ts / (float)CC;
        float var = t2 / (float)CC - mean * mean;
        mean_s[lane] = mean;
        rstd_s[lane] = rsqrtf(var + 1e-5f);
    }
    __syncthreads();
    uint32_t* yhb = yh + (size_t)b * L * CC;
    uint32_t* ylb = yl + (size_t)b * L * CC;
    for (int c0 = 0; c0 < CC; c0 += 32) {
        #pragma unroll
        for (int rr = 0; rr < 4; rr++) {
            int cr = wy * 4 + rr;
            tile[cr][lane] = xb[(size_t)(c0 + cr) * L + l0 + lane];
        }
        __syncthreads();
        #pragma unroll
        for (int rr = 0; rr < 4; rr++) {
            int r = wy * 4 + rr;     // l offset
            int c = c0 + lane;       // channel
            float v = tile[lane][r];
            float o = (v - mean_s[r]) * rstd_s[r] * gw[c] + bw[c];
            uint32_t h = f2tf32(o);
            yhb[(size_t)(l0 + r) * CC + c] = h;
            ylb[(size_t)(l0 + r) * CC + c] = f2tf32(o - __uint_as_float(h));
        }
        __syncthreads();
    }
}

// ---------------- final LN: x (b,L,512) -> out (b,512,L), + gamma + residual ----------------
__global__ void final_ln_t(const float* __restrict__ x, const float* __restrict__ gw,
                           const float* __restrict__ bw, const float* __restrict__ res,
                           const float* __restrict__ gamma, float* __restrict__ y) {
    int b = blockIdx.y;
    int l0 = blockIdx.x * 32;
    int lane = threadIdx.x, wy = threadIdx.y;
    const float* xb = x + (size_t)b * LQ * CC;
    __shared__ float mean_s[32], rstd_s[32];
    __shared__ float tile[32][33];
    #pragma unroll
    for (int rr = 0; rr < 4; rr++) {
        int r = wy * 4 + rr;
        const float* row = xb + (size_t)(l0 + r) * CC;
        float s = 0.f, s2 = 0.f;
        for (int c = lane; c < CC; c += 32) { float v = row[c]; s += v; s2 += v * v; }
        #pragma unroll
        for (int o = 16; o > 0; o >>= 1) {
            s += __shfl_xor_sync(0xFFFFFFFFu, s, o);
            s2 += __shfl_xor_sync(0xFFFFFFFFu, s2, o);
        }
        if (lane == 0) {
            float mean = s / (float)CC;
            float var = s2 / (float)CC - mean * mean;
            mean_s[r] = mean;
            rstd_s[r] = rsqrtf(var + 1e-5f);
        }
    }
    __syncthreads();
    float gm = gamma[0];
    const float* rb = res + (size_t)b * CC * LQ;
    float* yb = y + (size_t)b * CC * LQ;
    for (int c0 = 0; c0 < CC; c0 += 32) {
        #pragma unroll
        for (int rr = 0; rr < 4; rr++) {
            int r = wy * 4 + rr;
            tile[r][lane] = xb[(size_t)(l0 + r) * CC + c0 + lane];
        }
        __syncthreads();
        #pragma unroll
        for (int rr = 0; rr < 4; rr++) {
            int cr = wy * 4 + rr;
            int c = c0 + cr;
            float v = tile[lane][cr];
            float o = gm * ((v - mean_s[lane]) * rstd_s[lane] * gw[c] + bw[c])
                      + rb[(size_t)c * LQ + l0 + lane];
            yb[(size_t)c * LQ + l0 + lane] = o;
        }
        __syncthreads();
    }
}

// ---------------- pipelined 3xTF32 GEMM from pre-split hi/lo ----------------
// D[l][o] = sum_c X[l][c]*W[o][c]; X (M x 512) batched, W (N x 512).
// CTA 128x128, 8 warps (2m x 4n), KC=32 double-buffered via cp.async.
#define KC 32
#define LDA 36
#define TSZ (128 * LDA)
__global__ void __launch_bounds__(256) mma3p_gemm(const uint32_t* __restrict__ Xh,
                                                  const uint32_t* __restrict__ Xl,
                                                  const uint32_t* __restrict__ Wh,
                                                  const uint32_t* __restrict__ Wl,
                                                  float* __restrict__ Dout, int Ncols,
                                                  size_t xStride, size_t dStride) {
    extern __shared__ uint32_t sm[];
    uint32_t* Ah = sm;
    uint32_t* Al = sm + 2 * TSZ;
    uint32_t* Bh = sm + 4 * TSZ;
    uint32_t* Bl = sm + 6 * TSZ;
    int tid = threadIdx.x;
    int warp = tid >> 5, lane = tid & 31;
    int wm = warp & 1, wn = warp >> 1;
    int g = lane >> 2, t = lane & 3;
    int bn = blockIdx.x * 128, bm = blockIdx.y * 128, b = blockIdx.z;
    const uint32_t* Xbh = Xh + (size_t)b * xStride;
    const uint32_t* Xbl = Xl + (size_t)b * xStride;
    float* Db = Dout + (size_t)b * dStride;

    float acc[4][4][4];
    #pragma unroll
    for (int i = 0; i < 4; i++)
        #pragma unroll
        for (int j = 0; j < 4; j++)
            #pragma unroll
            for (int e = 0; e < 4; e++) acc[i][j][e] = 0.f;

    int lrow = tid >> 3;          // 0..31
    int lcol = (tid & 7) * 4;     // u32 col, 16B chunks

    auto load_stage = [&](int buf, int k0) {
        #pragma unroll
        for (int p = 0; p < 4; p++) {
            int row = p * 32 + lrow;
            size_t go = (size_t)(bm + row) * CC + k0 + lcol;
            size_t gw = (size_t)(bn + row) * CC + k0 + lcol;
            uint32_t so = (uint32_t)(buf * TSZ + row * LDA + lcol) * 4u;
            cpa16(smem_u32(Ah) + so, Xbh + go);
            cpa16(smem_u32(Al) + so, Xbl + go);
            cpa16(smem_u32(Bh) + so, Wh + gw);
            cpa16(smem_u32(Bl) + so, Wl + gw);
        }
        asm volatile("cp.async.commit_group;" ::: "memory");
    };

    load_stage(0, 0);
    for (int st = 0; st < 16; st++) {
        if (st + 1 < 16) {
            load_stage((st + 1) & 1, (st + 1) * KC);
            asm volatile("cp.async.wait_group 1;" ::: "memory");
        } else {
            asm volatile("cp.async.wait_group 0;" ::: "memory");
        }
        __syncthreads();
        int buf = st & 1;
        #pragma unroll
        for (int ks = 0; ks < 4; ks++) {
            int kk = ks * 8 + t;
            uint32_t ahi[4][4], alo[4][4];
            #pragma unroll
            for (int mt = 0; mt < 4; mt++) {
                int r = buf * TSZ + (wm * 64 + mt * 16 + g) * LDA + kk;
                ahi[mt][0] = Ah[r];
                ahi[mt][1] = Ah[r + 8 * LDA];
                ahi[mt][2] = Ah[r + 4];
                ahi[mt][3] = Ah[r + 8 * LDA + 4];
                alo[mt][0] = Al[r];
                alo[mt][1] = Al[r + 8 * LDA];
                alo[mt][2] = Al[r + 4];
                alo[mt][3] = Al[r + 8 * LDA + 4];
            }
            #pragma unroll
            for (int nt = 0; nt < 4; nt++) {
                int nb = buf * TSZ + (wn * 32 + nt * 8 + g) * LDA + kk;
                uint32_t bhi[2], blo[2];
                bhi[0] = Bh[nb]; bhi[1] = Bh[nb + 4];
                blo[0] = Bl[nb]; blo[1] = Bl[nb + 4];
                #pragma unroll
                for (int mt = 0; mt < 4; mt++) {
                    mma_tf32(acc[mt][nt], ahi[mt], bhi);
                    mma_tf32(acc[mt][nt], ahi[mt], blo);
                    mma_tf32(acc[mt][nt], alo[mt], bhi);
                }
            }
        }
        __syncthreads();
    }
    #pragma unroll
    for (int mt = 0; mt < 4; mt++) {
        int r0 = bm + wm * 64 + mt * 16 + g;
        #pragma unroll
        for (int nt = 0; nt < 4; nt++) {
            int c0 = bn + wn * 32 + nt * 8 + t * 2;
            *reinterpret_cast<float2*>(&Db[(size_t)r0 * Ncols + c0]) =
                make_float2(acc[mt][nt][0], acc[mt][nt][1]);
            *reinterpret_cast<float2*>(&Db[(size_t)(r0 + 8) * Ncols + c0]) =
                make_float2(acc[mt][nt][2], acc[mt][nt][3]);
        }
    }
}

// ---------------- L2 normalize groups of 64 within rows ----------------
__global__ void l2norm_groups(float* __restrict__ x, int rowStride) {
    int row = blockIdx.x;
    int h = threadIdx.y, lane = threadIdx.x;
    float* p = x + (size_t)row * rowStride + h * DD;
    float a = p[lane], b = p[lane + 32];
    float s = a * a + b * b;
    #pragma unroll
    for (int o = 16; o > 0; o >>= 1) s += __shfl_xor_sync(0xFFFFFFFFu, s, o);
    float inv = 1.0f / fmaxf(sqrtf(s), 1e-12f);
    p[lane] = a * inv;
    p[lane + 32] = b * inv;
}

// ---------------- gathers ----------------
__global__ void gather_qsmall() {
    int r = blockIdx.x * 8 + threadIdx.y;
    int bh = r >> 9;
    int b = bh >> 3, h = bh & 7;
    int idx = g_ridx[r];
    const float* s = g_dq + ((size_t)b * LQ + idx) * INNER + h * DD;
    float* d = g_qsm + (size_t)r * DD;
    d[threadIdx.x] = s[threadIdx.x];
    d[threadIdx.x + 32] = s[threadIdx.x + 32];
}

__global__ void gather_sel() {
    int r = blockIdx.x * 8 + threadIdx.y;
    int bh = r >> 9;
    int b = bh >> 3, h = bh & 7;
    int idx = g_sidx[r];
    const float* ks = g_dkv + ((size_t)b * LC + idx) * (2 * INNER) + h * DD;
    g_ksel[(size_t)r * DD + threadIdx.x] = ks[threadIdx.x];
    g_ksel[(size_t)r * DD + 32 + threadIdx.x] = ks[threadIdx.x + 32];
    g_vsel[(size_t)r * DD + threadIdx.x] = ks[INNER + threadIdx.x];
    g_vsel[(size_t)r * DD + 32 + threadIdx.x] = ks[INNER + threadIdx.x + 32];
}

// ---------------- L1 min-distance ----------------
__global__ void __launch_bounds__(256, 2) l1_min_kernel() {
    int bh = blockIdx.y;
    int b = bh >> 3, h = bh & 7;
    int kl = blockIdx.x * 256 + threadIdx.x;
    const ull* kp = reinterpret_cast<const ull*>(g_dkv + ((size_t)b * LC + kl) * (2 * INNER) + h * DD);
    ull kr2[32];
    #pragma unroll
    for (int i = 0; i < 32; i++) kr2[i] = kp[i];
    __shared__ float qs[128 * 64];
    const ull ABSM = 0x7FFFFFFF7FFFFFFFull;
    float best = 3.4e38f;
    for (int qc = 0; qc < TK; qc += 128) {
        const float4* qsrc4 = reinterpret_cast<const float4*>(g_qsm + ((size_t)bh * TK + qc) * DD);
        for (int j = threadIdx.x; j < 128 * 16; j += 256) {
            float4 v = qsrc4[j];
            reinterpret_cast<float4*>(qs)[j] = make_float4(-v.x, -v.y, -v.z, -v.w);
        }
        __syncthreads();
        for (int qq = 0; qq < 128; qq++) {
            const ull* qp = reinterpret_cast<const ull*>(qs + qq * 64);
            ull a0 = 0ull, a1 = 0ull, a2 = 0ull, a3 = 0ull;
            #pragma unroll
            for (int i = 0; i < 32; i += 4) {
                ull d0, d1, d2, d3;
                add2(d0, kr2[i + 0], qp[i + 0]); d0 &= ABSM; add2(a0, a0, d0);
                add2(d1, kr2[i + 1], qp[i + 1]); d1 &= ABSM; add2(a1, a1, d1);
                add2(d2, kr2[i + 2], qp[i + 2]); d2 &= ABSM; add2(a2, a2, d2);
                add2(d3, kr2[i + 3], qp[i + 3]); d3 &= ABSM; add2(a3, a3, d3);
            }
            ull s01, s23, s;
            add2(s01, a0, a1);
            add2(s23, a2, a3);
            add2(s, s01, s23);
            float2 f = unpack2(s);
            best = fminf(best, f.x + f.y);
        }
        __syncthreads();
    }
    g_mind[(size_t)bh * LC + kl] = best;
}

// ---------------- top-512 smallest via bitonic sort ----------------
__global__ void __launch_bounds__(1024) topk_kernel() {
    __shared__ ull keys[LC];
    int bh = blockIdx.x;
    int tid = threadIdx.x;
    for (int i = tid; i < LC; i += 1024) {
        unsigned fb = __float_as_uint(g_mind[(size_t)bh * LC + i]);
        keys[i] = ((ull)fb << 32) | (unsigned)i;
    }
    __syncthreads();
    for (int k = 2; k <= LC; k <<= 1) {
        for (int j = k >> 1; j > 0; j >>= 1) {
            for (int i = tid; i < LC; i += 1024) {
                int ixj = i ^ j;
                if (ixj > i) {
                    ull a = keys[i], bb = keys[ixj];
                    bool up = ((i & k) == 0);
                    if ((a > bb) == up) { keys[i] = bb; keys[ixj] = a; }
                }
            }
            __syncthreads();
        }
    }
    for (int i = tid; i < TK; i += 1024)
        g_sidx[bh * TK + i] = (int)(keys[i] & 0xFFFFFFFFu);
}

// ---------------- attention: emits tf32 hi/lo for out-GEMM ----------------
__global__ void __launch_bounds__(128) attn_kernel() {
    int bh = blockIdx.y;
    int b = bh >> 3, h = bh & 7;
    int ql = blockIdx.x * 128 + threadIdx.x;
    const ull* qp = reinterpret_cast<const ull*>(g_dq + ((size_t)b * LQ + ql) * INNER + h * DD);
    ull qr2[32];
    #pragma unroll
    for (int i = 0; i < 32; i++) qr2[i] = qp[i];
    ull num2[32];
    #pragma unroll
    for (int i = 0; i < 32; i++) num2[i] = 0ull;
    float den = 0.f;
    __shared__ float Ks[64 * 64];
    __shared__ float Vs[64 * 64];
    for (int kc = 0; kc < TK; kc += 64) {
        const float4* ksrc = reinterpret_cast<const float4*>(g_ksel + ((size_t)bh * TK + kc) * DD);
        const float4* vsrc = reinterpret_cast<const float4*>(g_vsel + ((size_t)bh * TK + kc) * DD);
        for (int j = threadIdx.x; j < 64 * 16; j += 128) {
            reinterpret_cast<float4*>(Ks)[j] = ksrc[j];
            reinterpret_cast<float4*>(Vs)[j] = vsrc[j];
        }
        __syncthreads();
        for (int kk = 0; kk < 64; kk++) {
            const ull* kp2 = reinterpret_cast<const ull*>(Ks + kk * 64);
            ull s0 = 0ull, s1 = 0ull, s2 = 0ull, s3 = 0ull;
            #pragma unroll
            for (int i = 0; i < 32; i += 4) {
                fma2(s0, qr2[i + 0], kp2[i + 0], s0);
                fma2(s1, qr2[i + 1], kp2[i + 1], s1);
                fma2(s2, qr2[i + 2], kp2[i + 2], s2);
                fma2(s3, qr2[i + 3], kp2[i + 3], s3);
            }
            ull sA, sB, sC;
            add2(sA, s0, s1);
            add2(sB, s2, s3);
            add2(sC, sA, sB);
            float2 f = unpack2(sC);
            float w = __expf(f.x + f.y);
            den += w;
            ull w2 = pack2(w, w);
            const ull* vp2 = reinterpret_cast<const ull*>(Vs + kk * 64);
            #pragma unroll
            for (int i = 0; i < 32; i++) fma2(num2[i], w2, vp2[i], num2[i]);
        }
        __syncthreads();
    }
    float inv = 1.0f / den;
    size_t ob = ((size_t)b * LQ + ql) * INNER + h * DD;
    #pragma unroll
    for (int i = 0; i < 32; i++) {
        float2 f = unpack2(num2[i]);
        float o0 = f.x * inv, o1 = f.y * inv;
        uint32_t h0 = f2tf32(o0), h1 = f2tf32(o1);
        g_aoh[ob + 2 * i] = h0;
        g_aoh[ob + 2 * i + 1] = h1;
        g_aol[ob + 2 * i] = f2tf32(o0 - __uint_as_float(h0));
        g_aol[ob + 2 * i + 1] = f2tf32(o1 - __uint_as_float(h1));
    }
}

// ---------------- host ----------------
extern "C" void kernel_launch(void* const* d_in, const int* in_sizes, int n_in,
                              void* d_out, int out_size) {
    (void)in_sizes; (void)n_in; (void)out_size;
    const float* qsrc  = (const float*)d_in[0];
    const float* ctx   = (const float*)d_in[1];
    const float* cn_g  = (const float*)d_in[2];
    const float* cn_b  = (const float*)d_in[3];
    const float* qn_g  = (const float*)d_in[4];
    const float* qn_b  = (const float*)d_in[5];
    const float* on_g  = (const float*)d_in[6];
    const float* on_b  = (const float*)d_in[7];
    const float* w_kv  = (const float*)d_in[8];
    const float* w_q   = (const float*)d_in[9];
    const float* w_out = (const float*)d_in[10];
    const float* gamma = (const float*)d_in[11];
    float* out = (float*)d_out;

    uint32_t *p_ctxh, *p_ctxl, *p_qsh, *p_qsl, *p_wkvh, *p_wkvl, *p_wqh, *p_wql,
             *p_woh, *p_wol, *p_aoh, *p_aol;
    float *p_dkv, *p_dq, *p_dout;
    cudaGetSymbolAddress((void**)&p_ctxh, g_ctxh);
    cudaGetSymbolAddress((void**)&p_ctxl, g_ctxl);
    cudaGetSymbolAddress((void**)&p_qsh, g_qsh);
    cudaGetSymbolAddress((void**)&p_qsl, g_qsl);
    cudaGetSymbolAddress((void**)&p_wkvh, g_wkvh);
    cudaGetSymbolAddress((void**)&p_wkvl, g_wkvl);
    cudaGetSymbolAddress((void**)&p_wqh, g_wqh);
    cudaGetSymbolAddress((void**)&p_wql, g_wql);
    cudaGetSymbolAddress((void**)&p_woh, g_woh);
    cudaGetSymbolAddress((void**)&p_wol, g_wol);
    cudaGetSymbolAddress((void**)&p_aoh, g_aoh);
    cudaGetSymbolAddress((void**)&p_aol, g_aol);
    cudaGetSymbolAddress((void**)&p_dkv, g_dkv);
    cudaGetSymbolAddress((void**)&p_dq, g_dq);
    cudaGetSymbolAddress((void**)&p_dout, g_dout);

    const int GEMM_SMEM = 8 * TSZ * 4;  // 147456 bytes
    cudaFuncSetAttribute(mma3p_gemm, cudaFuncAttributeMaxDynamicSharedMemorySize, GEMM_SMEM);

    dim3 thr328(32, 8);

    chan_ln_t<<<dim3(LC / 32, BB), thr328>>>(ctx, cn_g, cn_b, p_ctxh, p_ctxl, LC);
    chan_ln_t<<<dim3(LQ / 32, BB), thr328>>>(qsrc, qn_g, qn_b, p_qsh, p_qsl, LQ);

    split_kernel<<<(1024 * CC) / 256, 256>>>(w_kv, p_wkvh, p_wkvl, 1024 * CC);
    split_kernel<<<(INNER * CC) / 256, 256>>>(w_q, p_wqh, p_wql, INNER * CC);
    split_kernel<<<(CC * INNER) / 256, 256>>>(w_out, p_woh, p_wol, CC * INNER);

    mma3p_gemm<<<dim3(1024 / 128, LC / 128, BB), 256, GEMM_SMEM>>>(
        p_ctxh, p_ctxl, p_wkvh, p_wkvl, p_dkv, 1024, (size_t)LC * CC, (size_t)LC * 1024);
    mma3p_gemm<<<dim3(INNER / 128, LQ / 128, BB), 256, GEMM_SMEM>>>(
        p_qsh, p_qsl, p_wqh, p_wql, p_dq, INNER, (size_t)LQ * CC, (size_t)LQ * INNER);

    l2norm_groups<<<BB * LC, thr328>>>(p_dkv, 2 * INNER);
    l2norm_groups<<<BB * LQ, thr328>>>(p_dq, INNER);

    rng_kernel<<<32, 256>>>();
    gather_qsmall<<<BHH * TK / 8, thr328>>>();

    l1_min_kernel<<<dim3(LC / 256, BHH), 256>>>();
    topk_kernel<<<BHH, 1024>>>();
    gather_sel<<<BHH * TK / 8, thr328>>>();

    attn_kernel<<<dim3(LQ / 128, BHH), 128>>>();

    mma3p_gemm<<<dim3(INNER / 128, LQ / 128, BB), 256, GEMM_SMEM>>>(
        p_aoh, p_aol, p_woh, p_wol, p_dout, INNER, (size_t)LQ * INNER, (size_t)LQ * INNER);
    final_ln_t<<<dim3(LQ / 32, BB), thr328>>>(p_dout, on_g, on_b, qsrc, gamma, out);
}